// round 6
// baseline (speedup 1.0000x reference)
#include <cuda_runtime.h>
#include <math.h>

#define K_TOP    6000
#define CAND_CAP 16384
#define NMS_CAP  1024
#define HBINS    4096      // top 12 bits of transformed score
#define MSTRIDE  33        // padded mask row stride (no 32-way bank conflicts)
#define NGROUPS  16
#define NBLOCKS  148
#define NTHREADS 1024
#define CPW      4         // candidates per warp in rank phase
#define TILE     4096      // keys per smem tile in rank phase

// ---------------- scratch (device globals; no allocations) ----------------
__device__ unsigned int       g_hist[HBINS];
__device__ unsigned int       g_meta[8];     // [3] = candidate counter
__device__ unsigned long long g_cand[CAND_CAP];
__device__ float4             g_gbox[NGROUPS * NMS_CAP];
__device__ int                g_gpos[NGROUPS * NMS_CAP];
__device__ unsigned int       g_gcnt[NGROUPS];
__device__ unsigned int       g_barrier;     // monotonic ticket counter (never reset)

// order-preserving float<->uint transform
__device__ __forceinline__ unsigned int f2u(float f) {
    unsigned int b = __float_as_uint(f);
    return b ^ ((b & 0x80000000u) ? 0xFFFFFFFFu : 0x80000000u);
}
__device__ __forceinline__ float u2f(unsigned int u) {
    unsigned int b = (u & 0x80000000u) ? (u ^ 0x80000000u) : ~u;
    return __uint_as_float(b);
}

// grid-wide barrier: monotonic generation ticket; safe across graph replays.
// All NBLOCKS blocks are co-resident (1 block/SM by smem), so spinning is safe.
__device__ __forceinline__ void grid_sync() {
    __syncthreads();
    if (threadIdx.x == 0) {
        __threadfence();                                   // release
        unsigned int t = atomicAdd(&g_barrier, 1u);
        unsigned int target = (t / NBLOCKS + 1u) * NBLOCKS;
        while (true) {
            unsigned int v = *(volatile unsigned int*)&g_barrier;
            if ((int)(v - target) >= 0) break;             // wrap-safe
            __nanosleep(40);
        }
        __threadfence();                                   // acquire
    }
    __syncthreads();
}

__global__ __launch_bounds__(NTHREADS, 1)
void k_fused(const float* __restrict__ probs,
             const float* __restrict__ deltas,
             const float* __restrict__ anchors,
             float* __restrict__ out,
             int n_groups, int n_anchors) {
    extern __shared__ unsigned char dyn[];
    __shared__ unsigned int ssum[NTHREADS];
    __shared__ unsigned int s_t;
    __shared__ unsigned int s_remv[32];

    int tid  = threadIdx.x;
    int lane = tid & 31;
    int wid  = tid >> 5;
    unsigned int n_anch = (unsigned int)n_anchors;

    // ============ phase 1: 12-bit histogram of fg scores ============
    {
        unsigned int* sh = (unsigned int*)dyn;
        for (int k = tid; k < HBINS; k += NTHREADS) sh[k] = 0u;
        __syncthreads();

        const float4* __restrict__ p4 = (const float4*)probs;
        int stride = NBLOCKS * NTHREADS;
        for (int g = blockIdx.x * NTHREADS + tid; g < n_groups; g += stride) {
            float4 A = p4[g * 3 + 0], B = p4[g * 3 + 1], C = p4[g * 3 + 2];
            float s[8] = {A.y, A.z, B.x, B.y, B.w, C.x, C.z, C.w};
#pragma unroll
            for (int k = 0; k < 8; k++) {
                unsigned int bin = f2u(s[k]) >> 20;
                unsigned int act = __activemask();
                unsigned int peers = __match_any_sync(act, bin);
                int leader = __ffs(peers) - 1;
                if (lane == leader)
                    atomicAdd(&sh[bin], (unsigned int)__popc(peers));
            }
        }
        __syncthreads();
        for (int k = tid; k < HBINS; k += NTHREADS) {
            unsigned int v = sh[k];
            if (v) atomicAdd(&g_hist[k], v);
        }
    }
    grid_sync();

    // ============ phase 2: threshold + candidate collection ============
    {
        unsigned int cs = 0;
        int base = tid * (HBINS / NTHREADS);
#pragma unroll
        for (int k = 0; k < HBINS / NTHREADS; k++) cs += g_hist[base + k];
        ssum[tid] = cs; __syncthreads();
        for (int off = 1; off < NTHREADS; off <<= 1) {     // inclusive suffix sum
            unsigned int v = (tid + off < NTHREADS) ? ssum[tid + off] : 0u;
            __syncthreads();
            ssum[tid] += v;
            __syncthreads();
        }
        unsigned int excl = (tid < NTHREADS - 1) ? ssum[tid + 1] : 0u;
        if (ssum[tid] >= (unsigned)K_TOP && excl < (unsigned)K_TOP) {
            unsigned int run = excl;
            for (int k = HBINS / NTHREADS - 1; k >= 0; k--) {
                run += g_hist[base + k];
                if (run >= (unsigned)K_TOP) { s_t = (unsigned int)(base + k); break; }
            }
        }
        __syncthreads();
        unsigned int t = s_t;

        const float4* __restrict__ p4 = (const float4*)probs;
        int stride = NBLOCKS * NTHREADS;
        for (int g = blockIdx.x * NTHREADS + tid; g < n_groups; g += stride) {
            float4 A = p4[g * 3 + 0], B = p4[g * 3 + 1], C = p4[g * 3 + 2];
            float s[8] = {A.y, A.z, B.x, B.y, B.w, C.x, C.z, C.w};
#pragma unroll
            for (int k = 0; k < 8; k++) {
                unsigned int u = f2u(s[k]);
                bool e = (u >> 20) >= t;
                unsigned int act = __activemask();
                unsigned int ball = __ballot_sync(act, e);
                if (ball) {
                    int leader = __ffs(ball) - 1;
                    unsigned int posb = 0;
                    if (lane == leader)
                        posb = atomicAdd(&g_meta[3], (unsigned int)__popc(ball));
                    posb = __shfl_sync(act, posb, leader);
                    if (e) {
                        unsigned int my = posb + __popc(ball & ((1u << lane) - 1u));
                        if (my < CAND_CAP) {
                            unsigned int flat =
                                (unsigned int)((g * 4 + (k >> 1)) * 2 + (k & 1));
                            g_cand[my] = ((unsigned long long)u << 32) |
                                         (unsigned long long)(0xFFFFFFFFu - flat);
                        }
                    }
                }
            }
        }
    }
    grid_sync();

    // ============ phase 3: exact rank (global + within-group) + decode ============
    {
        unsigned long long* skeys = (unsigned long long*)dyn;          // TILE x u64
        unsigned int* sgrp = (unsigned int*)(skeys + TILE);            // TILE x u32

        int m = (int)min(g_meta[3], (unsigned int)CAND_CAP);
        int bc = blockIdx.x * (32 * CPW);

        unsigned long long ckey[CPW];
        unsigned int cgrp[CPW], cnt[CPW], cntg[CPW];
#pragma unroll
        for (int r = 0; r < CPW; r++) {
            int c = bc + wid * CPW + r;
            ckey[r] = (c < m) ? g_cand[c] : 0xFFFFFFFFFFFFFFFFULL;
            unsigned int flat = 0xFFFFFFFFu - (unsigned int)(ckey[r] & 0xFFFFFFFFu);
            unsigned int prop = flat >> 1;
            unsigned int b = 0;
#pragma unroll
            for (int q = 1; q < 8; q++) b += (prop >= q * n_anch) ? 1u : 0u;
            cgrp[r] = b * 2u + (flat & 1u);
            cnt[r] = 0u; cntg[r] = 0u;
        }

        int ntiles = (m + TILE - 1) / TILE;
        for (int tix = 0; tix < ntiles; tix++) {
            int t0 = tix * TILE;
            int nt = min(TILE, m - t0);
            for (int idx = tid; idx < nt; idx += NTHREADS) {
                unsigned long long key = g_cand[t0 + idx];
                skeys[idx] = key;
                unsigned int flat = 0xFFFFFFFFu - (unsigned int)(key & 0xFFFFFFFFu);
                unsigned int prop = flat >> 1;
                unsigned int b = 0;
#pragma unroll
                for (int q = 1; q < 8; q++) b += (prop >= q * n_anch) ? 1u : 0u;
                sgrp[idx] = b * 2u + (flat & 1u);
            }
            __syncthreads();
            if (bc < m) {
                for (int idx = lane; idx < nt; idx += 32) {
                    unsigned long long key = skeys[idx];
                    unsigned int gj = sgrp[idx];
#pragma unroll
                    for (int r = 0; r < CPW; r++) {
                        bool gt = (key > ckey[r]);
                        cnt[r]  += gt ? 1u : 0u;
                        cntg[r] += (gt && gj == cgrp[r]) ? 1u : 0u;
                    }
                }
            }
            __syncthreads();
        }

#pragma unroll
        for (int r = 0; r < CPW; r++) {
#pragma unroll
            for (int off = 16; off > 0; off >>= 1) {
                cnt[r]  += __shfl_down_sync(0xFFFFFFFFu, cnt[r], off);
                cntg[r] += __shfl_down_sync(0xFFFFFFFFu, cntg[r], off);
            }
        }

        if (lane == 0 && bc < m) {
#pragma unroll
            for (int r = 0; r < CPW; r++) {
                int c = bc + wid * CPW + r;
                if (c < m && cnt[r] < (unsigned)K_TOP) {
                    int rk = (int)cnt[r];
                    unsigned long long key = ckey[r];
                    unsigned int u = (unsigned int)(key >> 32);
                    unsigned int flat = 0xFFFFFFFFu - (unsigned int)(key & 0xFFFFFFFFu);
                    int prop = (int)(flat >> 1);
                    int cls = (int)(flat & 1u) + 1;
                    float score = u2f(u);
                    int b = prop / n_anchors;
                    int ai = prop - b * n_anchors;

                    const float* a  = anchors + (size_t)ai * 4;
                    const float* dl = deltas + (size_t)prop * 4;
                    float d0 = dl[0] * 0.1f, d1 = dl[1] * 0.1f;
                    float d2 = dl[2] * 0.2f, d3 = dl[3] * 0.2f;

                    const float inv = 1.0f / 512.0f;
                    float ay1 = a[0] * inv, ax1 = a[1] * inv;
                    float ay2 = a[2] * inv, ax2 = a[3] * inv;
                    float h  = ay2 - ay1;
                    float w2 = ax2 - ax1;
                    float cy = ay1 + 0.5f * h + d0 * h;
                    float cx = ax1 + 0.5f * w2 + d1 * w2;
                    h  = h * expf(d2);
                    w2 = w2 * expf(d3);
                    float y1 = cy - 0.5f * h;
                    float x1 = cx - 0.5f * w2;
                    float y2 = y1 + h;
                    float x2 = x1 + w2;
                    y1 = fminf(fmaxf(y1 * 512.0f, 0.0f), 512.0f);
                    x1 = fminf(fmaxf(x1 * 512.0f, 0.0f), 512.0f);
                    y2 = fminf(fmaxf(y2 * 512.0f, 0.0f), 512.0f);
                    x2 = fminf(fmaxf(x2 * 512.0f, 0.0f), 512.0f);

                    out[rk * 6 + 0] = y1;
                    out[rk * 6 + 1] = x1;
                    out[rk * 6 + 2] = y2;
                    out[rk * 6 + 3] = x2;
                    out[rk * 6 + 4] = score;
                    out[rk * 6 + 5] = 1.0f;
                    out[K_TOP * 6 + rk] = (float)cls;
                    out[K_TOP * 7 + rk] = (float)b;

                    int grp = b * 2 + (int)(flat & 1u);
                    unsigned int grank = cntg[r];
                    atomicAdd(&g_gcnt[grp], 1u);
                    if (grank < NMS_CAP) {
                        g_gbox[grp * NMS_CAP + grank] = make_float4(y1, x1, y2, x2);
                        g_gpos[grp * NMS_CAP + grank] = rk;
                    }
                }
            }
        }
    }
    grid_sync();

    // ============ phase 4: per-group NMS (blocks 0..15) + cleanup ============
    if (blockIdx.x >= NGROUPS) return;
    {
        float* sy1   = (float*)dyn;
        float* sx1   = sy1 + NMS_CAP;
        float* sy2   = sx1 + NMS_CAP;
        float* sx2   = sy2 + NMS_CAP;
        float* sarea = sx2 + NMS_CAP;
        int* spos    = (int*)(sarea + NMS_CAP);
        unsigned int* mask = (unsigned int*)(spos + NMS_CAP);  // [NMS_CAP][MSTRIDE]

        int grp = blockIdx.x;

        // cleanup scratch for next graph replay
        if (tid < HBINS / NGROUPS) g_hist[grp * (HBINS / NGROUPS) + tid] = 0u;
        if (grp == 0 && tid == 512) g_meta[3] = 0u;

        int n = min((int)g_gcnt[grp], NMS_CAP);

        for (int i = tid; i < n; i += NTHREADS) {
            float4 bx = g_gbox[grp * NMS_CAP + i];
            sy1[i] = bx.x; sx1[i] = bx.y; sy2[i] = bx.z; sx2[i] = bx.w;
            sarea[i] = (bx.z - bx.x + 1.0f) * (bx.w - bx.y + 1.0f);
            spos[i] = g_gpos[grp * NMS_CAP + i];
        }
        __syncthreads();
        if (tid == 0) g_gcnt[grp] = 0u;

        int nw = (n + 31) >> 5;

        // forward suppression masks; t = w*n + i (i fastest): lanes share w,
        // consecutive i -> conflict-free mask stores with MSTRIDE=33
        int total = nw * n;
        for (int t = tid; t < total; t += NTHREADS) {
            int w = t / n;
            int i = t - w * n;
            if (w < (i >> 5)) { mask[i * MSTRIDE + w] = 0u; continue; }
            float iy1 = sy1[i], ix1 = sx1[i], iy2 = sy2[i], ix2 = sx2[i];
            float ia = sarea[i];
            unsigned int mw = 0u;
            int jb = w << 5;
#pragma unroll 8
            for (int b = 0; b < 32; b++) {
                int j = jb + b;
                if (j > i && j < n) {
                    float ih  = fminf(iy2, sy2[j]) - fmaxf(iy1, sy1[j]) + 1.0f;
                    float iw2 = fminf(ix2, sx2[j]) - fmaxf(ix1, sx1[j]) + 1.0f;
                    ih = fmaxf(ih, 0.0f); iw2 = fmaxf(iw2, 0.0f);
                    float inter = ih * iw2;
                    if (inter >= 0.5f * (ia + sarea[j] - inter)) mw |= (1u << b);
                }
            }
            mask[i * MSTRIDE + w] = mw;
        }
        __syncthreads();

        // sequential greedy bit-reduce (warp 0); row prefetch off the chain
        if (tid < 32) {
            unsigned int remv = 0u;
            for (int i = 0; i < n; i++) {
                unsigned int row = (tid < nw) ? mask[i * MSTRIDE + tid] : 0u;
                unsigned int wv = __shfl_sync(0xFFFFFFFFu, remv, i >> 5);
                if (!((wv >> (i & 31)) & 1u)) remv |= row;
            }
            s_remv[tid] = remv;
        }
        __syncthreads();

        for (int j = tid; j < n; j += NTHREADS)
            out[spos[j] * 6 + 5] = ((s_remv[j >> 5] >> (j & 31)) & 1u) ? 0.0f : 1.0f;
    }
}

// ---------------- launch ----------------
extern "C" void kernel_launch(void* const* d_in, const int* in_sizes, int n_in,
                              void* d_out, int out_size) {
    const float* probs   = (const float*)d_in[0];
    const float* deltas  = (const float*)d_in[1];
    const float* anchors = (const float*)d_in[2];
    float* out = (float*)d_out;

    int n_prop    = in_sizes[0] / 3;
    int n_anchors = in_sizes[2] / 4;
    int n_groups  = n_prop / 4;

    // dynamic smem = max(phase1 16KB, phase3 48KB, phase4 ~153KB)
    const int smem = NMS_CAP * (5 * 4 + 4 + MSTRIDE * 4);   // 156672 bytes
    static int attr_set = 0;
    if (!attr_set) {
        cudaFuncSetAttribute(k_fused, cudaFuncAttributeMaxDynamicSharedMemorySize, smem);
        attr_set = 1;
    }

    k_fused<<<NBLOCKS, NTHREADS, smem>>>(probs, deltas, anchors, out,
                                         n_groups, n_anchors);
}

// round 7
// speedup vs baseline: 1.0061x; 1.0061x over previous
#include <cuda_runtime.h>
#include <math.h>

#define K_TOP    6000
#define CAND_CAP 16384
#define NMS_CAP  1024
#define HBINS    4096      // 12-bit histogram (top 12 bits of transformed score)
#define H2BINS   4096      // 12-bit refine histogram (bits [8,20))
#define MSTRIDE  33        // padded mask row stride (no 32-way bank conflicts)
#define NGROUPS  16

// ---------------- scratch (device globals; no allocations) ----------------
__device__ unsigned int       g_hist[HBINS];
__device__ unsigned int       g_hist2[H2BINS];
__device__ unsigned int       g_meta[8];     // [3] = candidate counter
__device__ unsigned long long g_cand[CAND_CAP];
__device__ float4             g_gbox[NGROUPS * NMS_CAP];
__device__ int                g_gpos[NGROUPS * NMS_CAP];
__device__ unsigned int       g_gcnt[NGROUPS];

// order-preserving float<->uint transform
__device__ __forceinline__ unsigned int f2u(float f) {
    unsigned int b = __float_as_uint(f);
    return b ^ ((b & 0x80000000u) ? 0xFFFFFFFFu : 0x80000000u);
}
__device__ __forceinline__ float u2f(unsigned int u) {
    unsigned int b = (u & 0x80000000u) ? (u ^ 0x80000000u) : ~u;
    return __uint_as_float(b);
}

// block-wide suffix-sum threshold find over a histogram H[bins], looking for
// the bin where the top-down running count crosses `need`.
// Returns via smem outputs: *o_t = crossing bin, *o_cnt = count strictly above it.
template<int BINS, int NT>
__device__ __forceinline__ void find_threshold(const unsigned int* H,
                                               unsigned int need,
                                               unsigned int* ssum,
                                               volatile unsigned int* o_t,
                                               volatile unsigned int* o_cnt) {
    int tid = threadIdx.x;
    const int bpt = BINS / NT;
    unsigned int cs = 0;
    int base = tid * bpt;
#pragma unroll
    for (int k = 0; k < bpt; k++) cs += H[base + k];
    ssum[tid] = cs; __syncthreads();
    for (int off = 1; off < NT; off <<= 1) {           // inclusive suffix sum
        unsigned int v = (tid + off < NT) ? ssum[tid + off] : 0u;
        __syncthreads();
        ssum[tid] += v;
        __syncthreads();
    }
    unsigned int excl = (tid < NT - 1) ? ssum[tid + 1] : 0u;
    if (ssum[tid] >= need && excl < need) {            // unique crossing chunk
        unsigned int run = excl;
        for (int k = bpt - 1; k >= 0; k--) {
            unsigned int h = H[base + k];
            if (run + h >= need) { *o_t = (unsigned int)(base + k); *o_cnt = run; break; }
            run += h;
        }
    }
    __syncthreads();
}

// ---------------- kernel 1: 12-bit histogram of fg scores ----------------
__global__ void k_hist(const float* __restrict__ probs, int n_groups) {
    __shared__ unsigned int sh[HBINS];
    for (int k = threadIdx.x; k < HBINS; k += blockDim.x) sh[k] = 0u;
    __syncthreads();

    const float4* __restrict__ p4 = (const float4*)probs;
    int stride = gridDim.x * blockDim.x;
    for (int g = blockIdx.x * blockDim.x + threadIdx.x; g < n_groups; g += stride) {
        float4 A = p4[g * 3 + 0], B = p4[g * 3 + 1], C = p4[g * 3 + 2];
        float s[8] = {A.y, A.z, B.x, B.y, B.w, C.x, C.z, C.w};
#pragma unroll
        for (int k = 0; k < 8; k++) {
            unsigned int bin = f2u(s[k]) >> 20;
            unsigned int act = __activemask();
            unsigned int peers = __match_any_sync(act, bin);
            int leader = __ffs(peers) - 1;
            if ((threadIdx.x & 31) == leader)
                atomicAdd(&sh[bin], (unsigned int)__popc(peers));
        }
    }
    __syncthreads();
    for (int k = threadIdx.x; k < HBINS; k += blockDim.x) {
        unsigned int v = sh[k];
        if (v) atomicAdd(&g_hist[k], v);
    }
}

// ---- kernel 2: refine histogram of the crossing bin's next 12 bits ----
__global__ void k_hist2(const float* __restrict__ probs, int n_groups) {
    __shared__ unsigned int sh[H2BINS];
    __shared__ unsigned int ssum[256];
    __shared__ unsigned int s_t, s_cnt;

    find_threshold<HBINS, 256>(g_hist, (unsigned)K_TOP, ssum, &s_t, &s_cnt);
    unsigned int t = s_t;

    for (int k = threadIdx.x; k < H2BINS; k += blockDim.x) sh[k] = 0u;
    __syncthreads();

    const float4* __restrict__ p4 = (const float4*)probs;
    int stride = gridDim.x * blockDim.x;
    for (int g = blockIdx.x * blockDim.x + threadIdx.x; g < n_groups; g += stride) {
        float4 A = p4[g * 3 + 0], B = p4[g * 3 + 1], C = p4[g * 3 + 2];
        float s[8] = {A.y, A.z, B.x, B.y, B.w, C.x, C.z, C.w};
#pragma unroll
        for (int k = 0; k < 8; k++) {
            unsigned int u = f2u(s[k]);
            if ((u >> 20) == t) {
                unsigned int bin = (u >> 8) & 0xFFFu;
                unsigned int act = __activemask();
                unsigned int peers = __match_any_sync(act, bin);
                int leader = __ffs(peers) - 1;
                if ((threadIdx.x & 31) == leader)
                    atomicAdd(&sh[bin], (unsigned int)__popc(peers));
            }
        }
    }
    __syncthreads();
    for (int k = threadIdx.x; k < H2BINS; k += blockDim.x) {
        unsigned int v = sh[k];
        if (v) atomicAdd(&g_hist2[k], v);
    }
}

// ------- kernel 3: 24-bit threshold + candidate collection -------
__global__ void k_collect(const float* __restrict__ probs, int n_groups) {
    __shared__ unsigned int ssum[256];
    __shared__ unsigned int s_t, s_cnt, s_t2, s_dum;
    int tid = threadIdx.x;
    int lane = tid & 31;

    find_threshold<HBINS, 256>(g_hist, (unsigned)K_TOP, ssum, &s_t, &s_cnt);
    unsigned int need2 = (unsigned)K_TOP - s_cnt;
    find_threshold<H2BINS, 256>(g_hist2, need2, ssum, &s_t2, &s_dum);
    unsigned int thr24 = (s_t << 12) | s_t2;

    const float4* __restrict__ p4 = (const float4*)probs;
    int stride = gridDim.x * blockDim.x;
    for (int g = blockIdx.x * blockDim.x + tid; g < n_groups; g += stride) {
        float4 A = p4[g * 3 + 0], B = p4[g * 3 + 1], C = p4[g * 3 + 2];
        float s[8] = {A.y, A.z, B.x, B.y, B.w, C.x, C.z, C.w};
#pragma unroll
        for (int k = 0; k < 8; k++) {
            unsigned int u = f2u(s[k]);
            bool e = (u >> 8) >= thr24;
            unsigned int act = __activemask();
            unsigned int ball = __ballot_sync(act, e);
            if (ball) {
                int leader = __ffs(ball) - 1;
                unsigned int posb = 0;
                if (lane == leader)
                    posb = atomicAdd(&g_meta[3], (unsigned int)__popc(ball));
                posb = __shfl_sync(act, posb, leader);
                if (e) {
                    unsigned int my = posb + __popc(ball & ((1u << lane) - 1u));
                    if (my < CAND_CAP) {
                        unsigned int flat = (unsigned int)((g * 4 + (k >> 1)) * 2 + (k & 1));
                        g_cand[my] = ((unsigned long long)u << 32) |
                                     (unsigned long long)(0xFFFFFFFFu - flat);
                    }
                }
            }
        }
    }
}

// --- kernel 4: warp-per-candidate exact rank (global + in-group) + decode ---
__global__ void k_rank(const float* __restrict__ deltas,
                       const float* __restrict__ anchors,
                       float* __restrict__ out, int n_anchors) {
    int m = (int)min(g_meta[3], (unsigned int)CAND_CAP);
    int lane = threadIdx.x & 31;
    int wgid = blockIdx.x * (blockDim.x >> 5) + (threadIdx.x >> 5);
    int nwarps = gridDim.x * (blockDim.x >> 5);
    unsigned int n_anch = (unsigned int)n_anchors;

    for (int c = wgid; c < m; c += nwarps) {
        unsigned long long ckey = g_cand[c];
        unsigned int cflat = 0xFFFFFFFFu - (unsigned int)(ckey & 0xFFFFFFFFu);
        unsigned int cprop = cflat >> 1;
        unsigned int cb = 0;
#pragma unroll
        for (int q = 1; q < 8; q++) cb += (cprop >= (unsigned)q * n_anch) ? 1u : 0u;
        unsigned int cgrp = cb * 2u + (cflat & 1u);

        unsigned int cnt = 0u, cntg = 0u;
        for (int j = lane; j < m; j += 32) {
            unsigned long long k = g_cand[j];
            if (k > ckey) {
                cnt++;
                unsigned int flat = 0xFFFFFFFFu - (unsigned int)(k & 0xFFFFFFFFu);
                unsigned int prop = flat >> 1;
                unsigned int b = 0;
#pragma unroll
                for (int q = 1; q < 8; q++) b += (prop >= (unsigned)q * n_anch) ? 1u : 0u;
                cntg += (b * 2u + (flat & 1u) == cgrp) ? 1u : 0u;
            }
        }
#pragma unroll
        for (int off = 16; off > 0; off >>= 1) {
            cnt  += __shfl_down_sync(0xFFFFFFFFu, cnt, off);
            cntg += __shfl_down_sync(0xFFFFFFFFu, cntg, off);
        }

        if (lane == 0 && cnt < (unsigned)K_TOP) {
            int rk = (int)cnt;
            unsigned int u = (unsigned int)(ckey >> 32);
            int prop = (int)cprop;
            int cls = (int)(cflat & 1u) + 1;
            float score = u2f(u);
            int b = (int)cb;
            int ai = prop - b * n_anchors;

            const float* a  = anchors + (size_t)ai * 4;
            const float* dl = deltas + (size_t)prop * 4;
            float d0 = dl[0] * 0.1f, d1 = dl[1] * 0.1f;
            float d2 = dl[2] * 0.2f, d3 = dl[3] * 0.2f;

            const float inv = 1.0f / 512.0f;
            float ay1 = a[0] * inv, ax1 = a[1] * inv;
            float ay2 = a[2] * inv, ax2 = a[3] * inv;
            float h  = ay2 - ay1;
            float w2 = ax2 - ax1;
            float cy = ay1 + 0.5f * h + d0 * h;
            float cx = ax1 + 0.5f * w2 + d1 * w2;
            h  = h * expf(d2);
            w2 = w2 * expf(d3);
            float y1 = cy - 0.5f * h;
            float x1 = cx - 0.5f * w2;
            float y2 = y1 + h;
            float x2 = x1 + w2;
            y1 = fminf(fmaxf(y1 * 512.0f, 0.0f), 512.0f);
            x1 = fminf(fmaxf(x1 * 512.0f, 0.0f), 512.0f);
            y2 = fminf(fmaxf(y2 * 512.0f, 0.0f), 512.0f);
            x2 = fminf(fmaxf(x2 * 512.0f, 0.0f), 512.0f);

            out[rk * 6 + 0] = y1;
            out[rk * 6 + 1] = x1;
            out[rk * 6 + 2] = y2;
            out[rk * 6 + 3] = x2;
            out[rk * 6 + 4] = score;
            out[rk * 6 + 5] = 1.0f;                 // keep (finalized by NMS)
            out[K_TOP * 6 + rk] = (float)cls;       // class_ids
            out[K_TOP * 7 + rk] = (float)b;         // batch ids

            int grp = b * 2 + (int)(cflat & 1u);
            atomicAdd(&g_gcnt[grp], 1u);
            if (cntg < NMS_CAP) {
                g_gbox[grp * NMS_CAP + cntg] = make_float4(y1, x1, y2, x2);
                g_gpos[grp * NMS_CAP + cntg] = rk;
            }
        }
    }
}

// ------- kernel 5: per-group NMS on pre-sorted boxes + scratch cleanup -------
// dynamic smem: sy1|sx1|sy2|sx2|sarea (f32 x NMS_CAP), spos (i32 x NMS_CAP),
//               mask (u32 x NMS_CAP x MSTRIDE)
__global__ void k_nms(float* __restrict__ out) {
    extern __shared__ unsigned char dyn[];
    float* sy1   = (float*)dyn;
    float* sx1   = sy1 + NMS_CAP;
    float* sy2   = sx1 + NMS_CAP;
    float* sx2   = sy2 + NMS_CAP;
    float* sarea = sx2 + NMS_CAP;
    int* spos    = (int*)(sarea + NMS_CAP);
    unsigned int* mask = (unsigned int*)(spos + NMS_CAP);   // [NMS_CAP][MSTRIDE]

    __shared__ unsigned int s_remv[32];

    int tid = threadIdx.x;
    int grp = blockIdx.x;

    // cleanup scratch for next graph replay
    if (tid < HBINS / NGROUPS) g_hist[grp * (HBINS / NGROUPS) + tid] = 0u;
    else if (tid >= 256 && tid < 256 + H2BINS / NGROUPS)
        g_hist2[grp * (H2BINS / NGROUPS) + (tid - 256)] = 0u;
    if (grp == 0 && tid == 512) g_meta[3] = 0u;

    int n = min((int)g_gcnt[grp], NMS_CAP);

    // load this group's pre-sorted boxes (coalesced float4)
    for (int i = tid; i < n; i += blockDim.x) {
        float4 bx = g_gbox[grp * NMS_CAP + i];
        sy1[i] = bx.x; sx1[i] = bx.y; sy2[i] = bx.z; sx2[i] = bx.w;
        sarea[i] = (bx.z - bx.x + 1.0f) * (bx.w - bx.y + 1.0f);
        spos[i] = g_gpos[grp * NMS_CAP + i];
    }
    __syncthreads();
    if (tid == 0) g_gcnt[grp] = 0u;

    int nw = (n + 31) >> 5;

    // forward suppression masks; t = w*n + i (i fastest): lanes share w,
    // consecutive i -> conflict-free mask stores with MSTRIDE=33
    int total = nw * n;
    for (int t = tid; t < total; t += blockDim.x) {
        int w = t / n;
        int i = t - w * n;
        if (w < (i >> 5)) { mask[i * MSTRIDE + w] = 0u; continue; }
        float iy1 = sy1[i], ix1 = sx1[i], iy2 = sy2[i], ix2 = sx2[i];
        float ia = sarea[i];
        unsigned int mw = 0u;
        int jb = w << 5;
#pragma unroll 8
        for (int b = 0; b < 32; b++) {
            int j = jb + b;
            if (j > i && j < n) {
                float ih  = fminf(iy2, sy2[j]) - fmaxf(iy1, sy1[j]) + 1.0f;
                float iw2 = fminf(ix2, sx2[j]) - fmaxf(ix1, sx1[j]) + 1.0f;
                ih = fmaxf(ih, 0.0f); iw2 = fmaxf(iw2, 0.0f);
                float inter = ih * iw2;
                if (inter >= 0.5f * (ia + sarea[j] - inter)) mw |= (1u << b);
            }
        }
        mask[i * MSTRIDE + w] = mw;
    }
    __syncthreads();

    // greedy bit-reduce (warp 0), skipping suppressed boxes via ffs over
    // the current chunk's alive word (uniform across lanes).
    if (tid < 32) {
        unsigned int remv = 0u;
        for (int c = 0; c < nw; c++) {
            unsigned int alive = ~__shfl_sync(0xFFFFFFFFu, remv, c);
            if (c == nw - 1 && (n & 31)) alive &= (1u << (n & 31)) - 1u;
            while (alive) {
                int b = __ffs(alive) - 1;
                int i = (c << 5) + b;
                unsigned int row = (tid < nw) ? mask[i * MSTRIDE + tid] : 0u;
                remv |= row;
                unsigned int rowc = __shfl_sync(0xFFFFFFFFu, row, c);
                alive &= ~rowc;
                alive &= ~(1u << b);
            }
        }
        s_remv[tid] = remv;
    }
    __syncthreads();

    for (int j = tid; j < n; j += blockDim.x)
        out[spos[j] * 6 + 5] = ((s_remv[j >> 5] >> (j & 31)) & 1u) ? 0.0f : 1.0f;
}

// ---------------- launch ----------------
extern "C" void kernel_launch(void* const* d_in, const int* in_sizes, int n_in,
                              void* d_out, int out_size) {
    const float* probs   = (const float*)d_in[0];
    const float* deltas  = (const float*)d_in[1];
    const float* anchors = (const float*)d_in[2];
    float* out = (float*)d_out;

    int n_prop    = in_sizes[0] / 3;
    int n_anchors = in_sizes[2] / 4;
    int n_groups  = n_prop / 4;          // 4 props (12 floats = 3 float4) per thread-step

    const int nms_smem = NMS_CAP * (5 * 4 + 4 + MSTRIDE * 4);   // 156672 bytes
    static int attr_set = 0;
    if (!attr_set) {
        cudaFuncSetAttribute(k_nms, cudaFuncAttributeMaxDynamicSharedMemorySize, nms_smem);
        attr_set = 1;
    }

    k_hist<<<148, 512>>>(probs, n_groups);
    k_hist2<<<296, 256>>>(probs, n_groups);
    k_collect<<<296, 256>>>(probs, n_groups);
    k_rank<<<512, 512>>>(deltas, anchors, out, n_anchors);
    k_nms<<<NGROUPS, 1024, nms_smem>>>(out);
}

// round 8
// speedup vs baseline: 1.3071x; 1.2992x over previous
#include <cuda_runtime.h>
#include <math.h>

#define K_TOP    6000
#define CAND_CAP 16384
#define NMS_CAP  1024
#define HBINS    4096      // 12-bit histogram (top 12 bits of transformed score)
#define H2BINS   4096      // 12-bit refine histogram (bits [8,20))
#define MSTRIDE  33        // padded mask row stride (no 32-way bank conflicts)
#define NGROUPS  16

// ---------------- scratch (device globals; no allocations) ----------------
__device__ unsigned int       g_hist[HBINS];
__device__ unsigned int       g_hist2[H2BINS];
__device__ unsigned int       g_meta[8];     // [3] = candidate counter
__device__ unsigned long long g_cand[CAND_CAP];
__device__ float4             g_gbox[NGROUPS * NMS_CAP];
__device__ int                g_gpos[NGROUPS * NMS_CAP];
__device__ unsigned int       g_gcnt[NGROUPS];

// order-preserving float<->uint transform
__device__ __forceinline__ unsigned int f2u(float f) {
    unsigned int b = __float_as_uint(f);
    return b ^ ((b & 0x80000000u) ? 0xFFFFFFFFu : 0x80000000u);
}
__device__ __forceinline__ float u2f(unsigned int u) {
    unsigned int b = (u & 0x80000000u) ? (u ^ 0x80000000u) : ~u;
    return __uint_as_float(b);
}

// block-wide suffix-sum threshold find over histogram H[BINS]: locate the bin
// where the top-down running count crosses `need`.
template<int BINS, int NT>
__device__ __forceinline__ void find_threshold(const unsigned int* H,
                                               unsigned int need,
                                               unsigned int* ssum,
                                               volatile unsigned int* o_t,
                                               volatile unsigned int* o_cnt) {
    int tid = threadIdx.x;
    const int bpt = BINS / NT;
    unsigned int cs = 0;
    int base = tid * bpt;
#pragma unroll
    for (int k = 0; k < bpt; k++) cs += H[base + k];
    ssum[tid] = cs; __syncthreads();
    for (int off = 1; off < NT; off <<= 1) {           // inclusive suffix sum
        unsigned int v = (tid + off < NT) ? ssum[tid + off] : 0u;
        __syncthreads();
        ssum[tid] += v;
        __syncthreads();
    }
    unsigned int excl = (tid < NT - 1) ? ssum[tid + 1] : 0u;
    if (ssum[tid] >= need && excl < need) {            // unique crossing chunk
        unsigned int run = excl;
        for (int k = bpt - 1; k >= 0; k--) {
            unsigned int h = H[base + k];
            if (run + h >= need) { *o_t = (unsigned int)(base + k); *o_cnt = run; break; }
            run += h;
        }
    }
    __syncthreads();
}

// ---------------- kernel 1: 12-bit histogram of fg scores ----------------
__global__ void k_hist(const float* __restrict__ probs, int n_groups) {
    __shared__ unsigned int sh[HBINS];
    for (int k = threadIdx.x; k < HBINS; k += blockDim.x) sh[k] = 0u;
    __syncthreads();

    const float4* __restrict__ p4 = (const float4*)probs;
    int stride = gridDim.x * blockDim.x;
    for (int g = blockIdx.x * blockDim.x + threadIdx.x; g < n_groups; g += stride) {
        float4 A = p4[g * 3 + 0], B = p4[g * 3 + 1], C = p4[g * 3 + 2];
        float s[8] = {A.y, A.z, B.x, B.y, B.w, C.x, C.z, C.w};
#pragma unroll
        for (int k = 0; k < 8; k++) {
            unsigned int bin = f2u(s[k]) >> 20;
            unsigned int act = __activemask();
            unsigned int peers = __match_any_sync(act, bin);
            int leader = __ffs(peers) - 1;
            if ((threadIdx.x & 31) == leader)
                atomicAdd(&sh[bin], (unsigned int)__popc(peers));
        }
    }
    __syncthreads();
    for (int k = threadIdx.x; k < HBINS; k += blockDim.x) {
        unsigned int v = sh[k];
        if (v) atomicAdd(&g_hist[k], v);
    }
}

// ---- kernel 2: refine histogram of the crossing bin's next 12 bits ----
__global__ void k_hist2(const float* __restrict__ probs, int n_groups) {
    __shared__ unsigned int sh[H2BINS];
    __shared__ unsigned int ssum[256];
    __shared__ unsigned int s_t, s_cnt;

    find_threshold<HBINS, 256>(g_hist, (unsigned)K_TOP, ssum, &s_t, &s_cnt);
    unsigned int t = s_t;

    for (int k = threadIdx.x; k < H2BINS; k += blockDim.x) sh[k] = 0u;
    __syncthreads();

    const float4* __restrict__ p4 = (const float4*)probs;
    int stride = gridDim.x * blockDim.x;
    for (int g = blockIdx.x * blockDim.x + threadIdx.x; g < n_groups; g += stride) {
        float4 A = p4[g * 3 + 0], B = p4[g * 3 + 1], C = p4[g * 3 + 2];
        float s[8] = {A.y, A.z, B.x, B.y, B.w, C.x, C.z, C.w};
#pragma unroll
        for (int k = 0; k < 8; k++) {
            unsigned int u = f2u(s[k]);
            if ((u >> 20) == t) {
                unsigned int bin = (u >> 8) & 0xFFFu;
                unsigned int act = __activemask();
                unsigned int peers = __match_any_sync(act, bin);
                int leader = __ffs(peers) - 1;
                if ((threadIdx.x & 31) == leader)
                    atomicAdd(&sh[bin], (unsigned int)__popc(peers));
            }
        }
    }
    __syncthreads();
    for (int k = threadIdx.x; k < H2BINS; k += blockDim.x) {
        unsigned int v = sh[k];
        if (v) atomicAdd(&g_hist2[k], v);
    }
}

// ------- kernel 3: 24-bit threshold + candidate collection -------
__global__ void k_collect(const float* __restrict__ probs, int n_groups) {
    __shared__ unsigned int ssum[256];
    __shared__ unsigned int s_t, s_cnt, s_t2, s_dum;
    int tid = threadIdx.x;
    int lane = tid & 31;

    find_threshold<HBINS, 256>(g_hist, (unsigned)K_TOP, ssum, &s_t, &s_cnt);
    unsigned int need2 = (unsigned)K_TOP - s_cnt;
    find_threshold<H2BINS, 256>(g_hist2, need2, ssum, &s_t2, &s_dum);
    unsigned int thr24 = (s_t << 12) | s_t2;

    const float4* __restrict__ p4 = (const float4*)probs;
    int stride = gridDim.x * blockDim.x;
    for (int g = blockIdx.x * blockDim.x + tid; g < n_groups; g += stride) {
        float4 A = p4[g * 3 + 0], B = p4[g * 3 + 1], C = p4[g * 3 + 2];
        float s[8] = {A.y, A.z, B.x, B.y, B.w, C.x, C.z, C.w};
#pragma unroll
        for (int k = 0; k < 8; k++) {
            unsigned int u = f2u(s[k]);
            bool e = (u >> 8) >= thr24;
            unsigned int act = __activemask();
            unsigned int ball = __ballot_sync(act, e);
            if (ball) {
                int leader = __ffs(ball) - 1;
                unsigned int posb = 0;
                if (lane == leader)
                    posb = atomicAdd(&g_meta[3], (unsigned int)__popc(ball));
                posb = __shfl_sync(act, posb, leader);
                if (e) {
                    unsigned int my = posb + __popc(ball & ((1u << lane) - 1u));
                    if (my < CAND_CAP) {
                        unsigned int flat = (unsigned int)((g * 4 + (k >> 1)) * 2 + (k & 1));
                        g_cand[my] = ((unsigned long long)u << 32) |
                                     (unsigned long long)(0xFFFFFFFFu - flat);
                    }
                }
            }
        }
    }
}

// --- kernel 4: 2-candidates-per-warp exact global rank + decode + group scatter ---
// Inner loop is a bare 64-bit compare-count (no group math). Within-group
// ordering is reconstructed in k_nms from the global ranks.
__global__ void k_rank(const float* __restrict__ deltas,
                       const float* __restrict__ anchors,
                       float* __restrict__ out, int n_anchors) {
    int m = (int)min(g_meta[3], (unsigned int)CAND_CAP);
    int lane = threadIdx.x & 31;
    int warp = blockIdx.x * (blockDim.x >> 5) + (threadIdx.x >> 5);
    int c0 = warp * 2;
    if (c0 >= m) return;

    unsigned long long ck0 = g_cand[c0];
    unsigned long long ck1 = (c0 + 1 < m) ? g_cand[c0 + 1] : 0xFFFFFFFFFFFFFFFFULL;
    unsigned int cnt0 = 0u, cnt1 = 0u;

    // scan keys as ulonglong2 pairs; slot m (if m odd) is provably 0 -> harmless
    const ulonglong2* __restrict__ p2 = (const ulonglong2*)g_cand;
    int mp = (m + 1) >> 1;
    for (int j = lane; j < mp; j += 32) {
        ulonglong2 kk = p2[j];
        cnt0 += (kk.x > ck0) ? 1u : 0u;
        cnt0 += (kk.y > ck0) ? 1u : 0u;
        cnt1 += (kk.x > ck1) ? 1u : 0u;
        cnt1 += (kk.y > ck1) ? 1u : 0u;
    }
#pragma unroll
    for (int off = 16; off > 0; off >>= 1) {
        cnt0 += __shfl_down_sync(0xFFFFFFFFu, cnt0, off);
        cnt1 += __shfl_down_sync(0xFFFFFFFFu, cnt1, off);
    }

    if (lane == 0) {
#pragma unroll
        for (int which = 0; which < 2; which++) {
            int c = c0 + which;
            if (c >= m) break;
            unsigned int cnt = which ? cnt1 : cnt0;
            if (cnt >= (unsigned)K_TOP) continue;
            unsigned long long ckey = which ? ck1 : ck0;

            int rk = (int)cnt;
            unsigned int u = (unsigned int)(ckey >> 32);
            unsigned int flat = 0xFFFFFFFFu - (unsigned int)(ckey & 0xFFFFFFFFu);
            int prop = (int)(flat >> 1);
            int cls = (int)(flat & 1u) + 1;
            float score = u2f(u);
            int b = prop / n_anchors;
            int ai = prop - b * n_anchors;

            const float* a  = anchors + (size_t)ai * 4;
            const float* dl = deltas + (size_t)prop * 4;
            float d0 = dl[0] * 0.1f, d1 = dl[1] * 0.1f;
            float d2 = dl[2] * 0.2f, d3 = dl[3] * 0.2f;

            const float inv = 1.0f / 512.0f;
            float ay1 = a[0] * inv, ax1 = a[1] * inv;
            float ay2 = a[2] * inv, ax2 = a[3] * inv;
            float h  = ay2 - ay1;
            float w2 = ax2 - ax1;
            float cy = ay1 + 0.5f * h + d0 * h;
            float cx = ax1 + 0.5f * w2 + d1 * w2;
            h  = h * expf(d2);
            w2 = w2 * expf(d3);
            float y1 = cy - 0.5f * h;
            float x1 = cx - 0.5f * w2;
            float y2 = y1 + h;
            float x2 = x1 + w2;
            y1 = fminf(fmaxf(y1 * 512.0f, 0.0f), 512.0f);
            x1 = fminf(fmaxf(x1 * 512.0f, 0.0f), 512.0f);
            y2 = fminf(fmaxf(y2 * 512.0f, 0.0f), 512.0f);
            x2 = fminf(fmaxf(x2 * 512.0f, 0.0f), 512.0f);

            out[rk * 6 + 0] = y1;
            out[rk * 6 + 1] = x1;
            out[rk * 6 + 2] = y2;
            out[rk * 6 + 3] = x2;
            out[rk * 6 + 4] = score;
            out[rk * 6 + 5] = 1.0f;                 // keep (finalized by NMS)
            out[K_TOP * 6 + rk] = (float)cls;       // class_ids
            out[K_TOP * 7 + rk] = (float)b;         // batch ids

            int grp = b * 2 + (int)(flat & 1u);
            unsigned int slot = atomicAdd(&g_gcnt[grp], 1u);   // arbitrary order
            if (slot < NMS_CAP) {
                g_gbox[grp * NMS_CAP + slot] = make_float4(y1, x1, y2, x2);
                g_gpos[grp * NMS_CAP + slot] = rk;
            }
        }
    }
}

// ------- kernel 5: per-group NMS (sorts by global rank first) + cleanup -------
// dynamic smem: sy1|sx1|sy2|sx2|sarea (f32 x NMS_CAP), spos (i32 x NMS_CAP),
//               mask (u32 x NMS_CAP x MSTRIDE); mask head doubles as rk scratch
__global__ void k_nms(float* __restrict__ out) {
    extern __shared__ unsigned char dyn[];
    float* sy1   = (float*)dyn;
    float* sx1   = sy1 + NMS_CAP;
    float* sy2   = sx1 + NMS_CAP;
    float* sx2   = sy2 + NMS_CAP;
    float* sarea = sx2 + NMS_CAP;
    int* spos    = (int*)(sarea + NMS_CAP);
    unsigned int* mask = (unsigned int*)(spos + NMS_CAP);   // [NMS_CAP][MSTRIDE]
    int* rkraw = (int*)mask;                                // pre-mask scratch

    __shared__ unsigned int s_remv[32];

    int tid = threadIdx.x;
    int grp = blockIdx.x;

    // cleanup scratch for next graph replay
    if (tid < HBINS / NGROUPS) g_hist[grp * (HBINS / NGROUPS) + tid] = 0u;
    else if (tid >= 256 && tid < 256 + H2BINS / NGROUPS)
        g_hist2[grp * (H2BINS / NGROUPS) + (tid - 256)] = 0u;
    if (grp == 0 && tid == 512) g_meta[3] = 0u;

    int n = min((int)g_gcnt[grp], NMS_CAP);

    // load raw (unordered) entries; sort by global rank via rank-by-count
    float4 bx = make_float4(0.f, 0.f, 0.f, 0.f);
    int ps = 0;
    if (tid < n) {
        bx = g_gbox[grp * NMS_CAP + tid];
        ps = g_gpos[grp * NMS_CAP + tid];
        rkraw[tid] = ps;
    }
    __syncthreads();
    if (tid == 0) g_gcnt[grp] = 0u;
    int myrank = 0;
    if (tid < n)
        for (int j = 0; j < n; j++) myrank += (rkraw[j] < ps) ? 1 : 0;
    __syncthreads();
    if (tid < n) {
        sy1[myrank] = bx.x; sx1[myrank] = bx.y;
        sy2[myrank] = bx.z; sx2[myrank] = bx.w;
        sarea[myrank] = (bx.z - bx.x + 1.0f) * (bx.w - bx.y + 1.0f);
        spos[myrank] = ps;
    }
    __syncthreads();

    int nw = (n + 31) >> 5;

    // forward suppression masks; t = w*n + i (i fastest): lanes share w,
    // consecutive i -> conflict-free mask stores with MSTRIDE=33
    int total = nw * n;
    for (int t = tid; t < total; t += blockDim.x) {
        int w = t / n;
        int i = t - w * n;
        if (w < (i >> 5)) { mask[i * MSTRIDE + w] = 0u; continue; }
        float iy1 = sy1[i], ix1 = sx1[i], iy2 = sy2[i], ix2 = sx2[i];
        float ia = sarea[i];
        unsigned int mw = 0u;
        int jb = w << 5;
#pragma unroll 8
        for (int b = 0; b < 32; b++) {
            int j = jb + b;
            if (j > i && j < n) {
                float ih  = fminf(iy2, sy2[j]) - fmaxf(iy1, sy1[j]) + 1.0f;
                float iw2 = fminf(ix2, sx2[j]) - fmaxf(ix1, sx1[j]) + 1.0f;
                ih = fmaxf(ih, 0.0f); iw2 = fmaxf(iw2, 0.0f);
                float inter = ih * iw2;
                if (inter >= 0.5f * (ia + sarea[j] - inter)) mw |= (1u << b);
            }
        }
        mask[i * MSTRIDE + w] = mw;
    }
    __syncthreads();

    // greedy bit-reduce (warp 0), visiting only still-alive boxes via ffs
    if (tid < 32) {
        unsigned int remv = 0u;
        for (int c = 0; c < nw; c++) {
            unsigned int alive = ~__shfl_sync(0xFFFFFFFFu, remv, c);
            if (c == nw - 1 && (n & 31)) alive &= (1u << (n & 31)) - 1u;
            while (alive) {
                int b = __ffs(alive) - 1;
                int i = (c << 5) + b;
                unsigned int row = (tid < nw) ? mask[i * MSTRIDE + tid] : 0u;
                remv |= row;
                unsigned int rowc = __shfl_sync(0xFFFFFFFFu, row, c);
                alive &= ~rowc;
                alive &= ~(1u << b);
            }
        }
        s_remv[tid] = remv;
    }
    __syncthreads();

    for (int j = tid; j < n; j += blockDim.x)
        out[spos[j] * 6 + 5] = ((s_remv[j >> 5] >> (j & 31)) & 1u) ? 0.0f : 1.0f;
}

// ---------------- launch ----------------
extern "C" void kernel_launch(void* const* d_in, const int* in_sizes, int n_in,
                              void* d_out, int out_size) {
    const float* probs   = (const float*)d_in[0];
    const float* deltas  = (const float*)d_in[1];
    const float* anchors = (const float*)d_in[2];
    float* out = (float*)d_out;

    int n_prop    = in_sizes[0] / 3;
    int n_anchors = in_sizes[2] / 4;
    int n_groups  = n_prop / 4;          // 4 props (12 floats = 3 float4) per thread-step

    const int nms_smem = NMS_CAP * (5 * 4 + 4 + MSTRIDE * 4);   // 156672 bytes
    static int attr_set = 0;
    if (!attr_set) {
        cudaFuncSetAttribute(k_nms, cudaFuncAttributeMaxDynamicSharedMemorySize, nms_smem);
        attr_set = 1;
    }

    k_hist<<<148, 512>>>(probs, n_groups);
    k_hist2<<<296, 256>>>(probs, n_groups);
    k_collect<<<296, 256>>>(probs, n_groups);
    k_rank<<<256, 512>>>(deltas, anchors, out, n_anchors);
    k_nms<<<NGROUPS, 1024, nms_smem>>>(out);
}

// round 9
// speedup vs baseline: 1.3092x; 1.0016x over previous
#include <cuda_runtime.h>
#include <math.h>

#define K_TOP    6000
#define CAND_CAP 16384
#define NMS_CAP  1024
#define HBINS    4096      // 12-bit histogram (top 12 bits of transformed score)
#define H2BINS   4096      // 12-bit refine histogram (bits [8,20))
#define MSTRIDE  33        // padded mask row stride (no 32-way bank conflicts)
#define NGROUPS  16
#define RTILE    1024      // ulonglong2 pairs per rank smem tile

// ---------------- scratch (device globals; no allocations) ----------------
__device__ unsigned int       g_hist[HBINS];
__device__ unsigned int       g_hist2[H2BINS];
__device__ unsigned int       g_meta[8];     // [3] = candidate counter
__device__ unsigned long long g_cand[CAND_CAP];
__device__ float4             g_gbox[NGROUPS * NMS_CAP];
__device__ int                g_gpos[NGROUPS * NMS_CAP];
__device__ unsigned int       g_gcnt[NGROUPS];

// order-preserving float<->uint transform
__device__ __forceinline__ unsigned int f2u(float f) {
    unsigned int b = __float_as_uint(f);
    return b ^ ((b & 0x80000000u) ? 0xFFFFFFFFu : 0x80000000u);
}
__device__ __forceinline__ float u2f(unsigned int u) {
    unsigned int b = (u & 0x80000000u) ? (u ^ 0x80000000u) : ~u;
    return __uint_as_float(b);
}

// block-wide suffix-sum threshold find over histogram H[BINS]
template<int BINS, int NT>
__device__ __forceinline__ void find_threshold(const unsigned int* H,
                                               unsigned int need,
                                               unsigned int* ssum,
                                               volatile unsigned int* o_t,
                                               volatile unsigned int* o_cnt) {
    int tid = threadIdx.x;
    const int bpt = BINS / NT;
    unsigned int cs = 0;
    int base = tid * bpt;
#pragma unroll
    for (int k = 0; k < bpt; k++) cs += H[base + k];
    ssum[tid] = cs; __syncthreads();
    for (int off = 1; off < NT; off <<= 1) {           // inclusive suffix sum
        unsigned int v = (tid + off < NT) ? ssum[tid + off] : 0u;
        __syncthreads();
        ssum[tid] += v;
        __syncthreads();
    }
    unsigned int excl = (tid < NT - 1) ? ssum[tid + 1] : 0u;
    if (ssum[tid] >= need && excl < need) {            // unique crossing chunk
        unsigned int run = excl;
        for (int k = bpt - 1; k >= 0; k--) {
            unsigned int h = H[base + k];
            if (run + h >= need) { *o_t = (unsigned int)(base + k); *o_cnt = run; break; }
            run += h;
        }
    }
    __syncthreads();
}

// ---------------- kernel 1: 12-bit histogram of fg scores ----------------
__global__ void k_hist(const float* __restrict__ probs, int n_groups) {
    __shared__ unsigned int sh[HBINS];
    for (int k = threadIdx.x; k < HBINS; k += blockDim.x) sh[k] = 0u;
    __syncthreads();

    const float4* __restrict__ p4 = (const float4*)probs;
    int stride = gridDim.x * blockDim.x;
    for (int g = blockIdx.x * blockDim.x + threadIdx.x; g < n_groups; g += stride) {
        float4 A = p4[g * 3 + 0], B = p4[g * 3 + 1], C = p4[g * 3 + 2];
        float s[8] = {A.y, A.z, B.x, B.y, B.w, C.x, C.z, C.w};
#pragma unroll
        for (int k = 0; k < 8; k++) {
            unsigned int bin = f2u(s[k]) >> 20;
            unsigned int act = __activemask();
            unsigned int peers = __match_any_sync(act, bin);
            int leader = __ffs(peers) - 1;
            if ((threadIdx.x & 31) == leader)
                atomicAdd(&sh[bin], (unsigned int)__popc(peers));
        }
    }
    __syncthreads();
    for (int k = threadIdx.x; k < HBINS; k += blockDim.x) {
        unsigned int v = sh[k];
        if (v) atomicAdd(&g_hist[k], v);
    }
}

// ---- kernel 2: refine histogram of the crossing bin's next 12 bits ----
__global__ void k_hist2(const float* __restrict__ probs, int n_groups) {
    __shared__ unsigned int sh[H2BINS];
    __shared__ unsigned int ssum[256];
    __shared__ unsigned int s_t, s_cnt;

    find_threshold<HBINS, 256>(g_hist, (unsigned)K_TOP, ssum, &s_t, &s_cnt);
    unsigned int t = s_t;

    for (int k = threadIdx.x; k < H2BINS; k += blockDim.x) sh[k] = 0u;
    __syncthreads();

    const float4* __restrict__ p4 = (const float4*)probs;
    int stride = gridDim.x * blockDim.x;
    for (int g = blockIdx.x * blockDim.x + threadIdx.x; g < n_groups; g += stride) {
        float4 A = p4[g * 3 + 0], B = p4[g * 3 + 1], C = p4[g * 3 + 2];
        float s[8] = {A.y, A.z, B.x, B.y, B.w, C.x, C.z, C.w};
#pragma unroll
        for (int k = 0; k < 8; k++) {
            unsigned int u = f2u(s[k]);
            if ((u >> 20) == t) {
                unsigned int bin = (u >> 8) & 0xFFFu;
                unsigned int act = __activemask();
                unsigned int peers = __match_any_sync(act, bin);
                int leader = __ffs(peers) - 1;
                if ((threadIdx.x & 31) == leader)
                    atomicAdd(&sh[bin], (unsigned int)__popc(peers));
            }
        }
    }
    __syncthreads();
    for (int k = threadIdx.x; k < H2BINS; k += blockDim.x) {
        unsigned int v = sh[k];
        if (v) atomicAdd(&g_hist2[k], v);
    }
}

// ------- kernel 3: 24-bit threshold + candidate collection -------
__global__ void k_collect(const float* __restrict__ probs, int n_groups) {
    __shared__ unsigned int ssum[256];
    __shared__ unsigned int s_t, s_cnt, s_t2, s_dum;
    int tid = threadIdx.x;
    int lane = tid & 31;

    find_threshold<HBINS, 256>(g_hist, (unsigned)K_TOP, ssum, &s_t, &s_cnt);
    unsigned int need2 = (unsigned)K_TOP - s_cnt;
    find_threshold<H2BINS, 256>(g_hist2, need2, ssum, &s_t2, &s_dum);
    unsigned int thr24 = (s_t << 12) | s_t2;

    const float4* __restrict__ p4 = (const float4*)probs;
    int stride = gridDim.x * blockDim.x;
    for (int g = blockIdx.x * blockDim.x + tid; g < n_groups; g += stride) {
        float4 A = p4[g * 3 + 0], B = p4[g * 3 + 1], C = p4[g * 3 + 2];
        float s[8] = {A.y, A.z, B.x, B.y, B.w, C.x, C.z, C.w};
#pragma unroll
        for (int k = 0; k < 8; k++) {
            unsigned int u = f2u(s[k]);
            bool e = (u >> 8) >= thr24;
            unsigned int act = __activemask();
            unsigned int ball = __ballot_sync(act, e);
            if (ball) {
                int leader = __ffs(ball) - 1;
                unsigned int posb = 0;
                if (lane == leader)
                    posb = atomicAdd(&g_meta[3], (unsigned int)__popc(ball));
                posb = __shfl_sync(act, posb, leader);
                if (e) {
                    unsigned int my = posb + __popc(ball & ((1u << lane) - 1u));
                    if (my < CAND_CAP) {
                        unsigned int flat = (unsigned int)((g * 4 + (k >> 1)) * 2 + (k & 1));
                        g_cand[my] = ((unsigned long long)u << 32) |
                                     (unsigned long long)(0xFFFFFFFFu - flat);
                    }
                }
            }
        }
    }
}

// --- kernel 4: exact global rank via smem-tiled compare-count + decode ---
// 2 candidates per warp, 32 warps/block; keys streamed through smem tiles
// once per BLOCK (not per warp). One wave (128 blocks).
__global__ __launch_bounds__(1024, 1)
void k_rank(const float* __restrict__ deltas,
            const float* __restrict__ anchors,
            float* __restrict__ out, int n_anchors) {
    __shared__ ulonglong2 tile[RTILE];      // 16KB
    int m = (int)min(g_meta[3], (unsigned int)CAND_CAP);
    int lane = threadIdx.x & 31;
    int wid  = threadIdx.x >> 5;
    int c0 = (blockIdx.x * 32 + wid) * 2;

    unsigned long long ck0 = (c0 < m)     ? g_cand[c0]     : 0xFFFFFFFFFFFFFFFFULL;
    unsigned long long ck1 = (c0 + 1 < m) ? g_cand[c0 + 1] : 0xFFFFFFFFFFFFFFFFULL;
    unsigned int cnt0 = 0u, cnt1 = 0u;

    const ulonglong2* __restrict__ p2 = (const ulonglong2*)g_cand;
    int mp = (m + 1) >> 1;                  // pairs; pad slot m is provably 0
    for (int t0 = 0; t0 < mp; t0 += RTILE) {
        int nt = min(RTILE, mp - t0);
        if (threadIdx.x < nt) tile[threadIdx.x] = p2[t0 + threadIdx.x];
        __syncthreads();
        for (int j = lane; j < nt; j += 32) {
            ulonglong2 kk = tile[j];
            cnt0 += (kk.x > ck0) ? 1u : 0u;
            cnt0 += (kk.y > ck0) ? 1u : 0u;
            cnt1 += (kk.x > ck1) ? 1u : 0u;
            cnt1 += (kk.y > ck1) ? 1u : 0u;
        }
        __syncthreads();
    }
#pragma unroll
    for (int off = 16; off > 0; off >>= 1) {
        cnt0 += __shfl_down_sync(0xFFFFFFFFu, cnt0, off);
        cnt1 += __shfl_down_sync(0xFFFFFFFFu, cnt1, off);
    }

    if (lane == 0 && c0 < m) {
#pragma unroll
        for (int which = 0; which < 2; which++) {
            int c = c0 + which;
            if (c >= m) break;
            unsigned int cnt = which ? cnt1 : cnt0;
            if (cnt >= (unsigned)K_TOP) continue;
            unsigned long long ckey = which ? ck1 : ck0;

            int rk = (int)cnt;
            unsigned int u = (unsigned int)(ckey >> 32);
            unsigned int flat = 0xFFFFFFFFu - (unsigned int)(ckey & 0xFFFFFFFFu);
            int prop = (int)(flat >> 1);
            int cls = (int)(flat & 1u) + 1;
            float score = u2f(u);
            int b = prop / n_anchors;
            int ai = prop - b * n_anchors;

            const float* a  = anchors + (size_t)ai * 4;
            const float* dl = deltas + (size_t)prop * 4;
            float d0 = dl[0] * 0.1f, d1 = dl[1] * 0.1f;
            float d2 = dl[2] * 0.2f, d3 = dl[3] * 0.2f;

            const float inv = 1.0f / 512.0f;
            float ay1 = a[0] * inv, ax1 = a[1] * inv;
            float ay2 = a[2] * inv, ax2 = a[3] * inv;
            float h  = ay2 - ay1;
            float w2 = ax2 - ax1;
            float cy = ay1 + 0.5f * h + d0 * h;
            float cx = ax1 + 0.5f * w2 + d1 * w2;
            h  = h * expf(d2);
            w2 = w2 * expf(d3);
            float y1 = cy - 0.5f * h;
            float x1 = cx - 0.5f * w2;
            float y2 = y1 + h;
            float x2 = x1 + w2;
            y1 = fminf(fmaxf(y1 * 512.0f, 0.0f), 512.0f);
            x1 = fminf(fmaxf(x1 * 512.0f, 0.0f), 512.0f);
            y2 = fminf(fmaxf(y2 * 512.0f, 0.0f), 512.0f);
            x2 = fminf(fmaxf(x2 * 512.0f, 0.0f), 512.0f);

            out[rk * 6 + 0] = y1;
            out[rk * 6 + 1] = x1;
            out[rk * 6 + 2] = y2;
            out[rk * 6 + 3] = x2;
            out[rk * 6 + 4] = score;
            out[rk * 6 + 5] = 1.0f;                 // keep (finalized by NMS)
            out[K_TOP * 6 + rk] = (float)cls;       // class_ids
            out[K_TOP * 7 + rk] = (float)b;         // batch ids

            int grp = b * 2 + (int)(flat & 1u);
            unsigned int slot = atomicAdd(&g_gcnt[grp], 1u);   // arbitrary order
            if (slot < NMS_CAP) {
                g_gbox[grp * NMS_CAP + slot] = make_float4(y1, x1, y2, x2);
                g_gpos[grp * NMS_CAP + slot] = rk;
            }
        }
    }
}

// ------- kernel 5: per-group NMS (sorts by global rank first) + cleanup -------
__global__ void k_nms(float* __restrict__ out) {
    extern __shared__ unsigned char dyn[];
    float* sy1   = (float*)dyn;
    float* sx1   = sy1 + NMS_CAP;
    float* sy2   = sx1 + NMS_CAP;
    float* sx2   = sy2 + NMS_CAP;
    float* sarea = sx2 + NMS_CAP;
    int* spos    = (int*)(sarea + NMS_CAP);
    unsigned int* mask = (unsigned int*)(spos + NMS_CAP);   // [NMS_CAP][MSTRIDE]
    int* rkraw = (int*)mask;                                // pre-mask scratch

    __shared__ unsigned int s_remv[32];

    int tid = threadIdx.x;
    int grp = blockIdx.x;

    // cleanup scratch for next graph replay
    if (tid < HBINS / NGROUPS) g_hist[grp * (HBINS / NGROUPS) + tid] = 0u;
    else if (tid >= 256 && tid < 256 + H2BINS / NGROUPS)
        g_hist2[grp * (H2BINS / NGROUPS) + (tid - 256)] = 0u;
    if (grp == 0 && tid == 512) g_meta[3] = 0u;

    int n = min((int)g_gcnt[grp], NMS_CAP);

    // load raw (unordered) entries; sort by global rank via rank-by-count
    float4 bx = make_float4(0.f, 0.f, 0.f, 0.f);
    int ps = 0;
    if (tid < n) {
        bx = g_gbox[grp * NMS_CAP + tid];
        ps = g_gpos[grp * NMS_CAP + tid];
        rkraw[tid] = ps;
    }
    __syncthreads();
    if (tid == 0) g_gcnt[grp] = 0u;
    int myrank = 0;
    if (tid < n)
        for (int j = 0; j < n; j++) myrank += (rkraw[j] < ps) ? 1 : 0;
    __syncthreads();
    if (tid < n) {
        sy1[myrank] = bx.x; sx1[myrank] = bx.y;
        sy2[myrank] = bx.z; sx2[myrank] = bx.w;
        sarea[myrank] = (bx.z - bx.x + 1.0f) * (bx.w - bx.y + 1.0f);
        spos[myrank] = ps;
    }
    __syncthreads();

    int nw = (n + 31) >> 5;

    // forward suppression masks; t = w*n + i (i fastest): lanes share w,
    // consecutive i -> conflict-free mask stores with MSTRIDE=33
    int total = nw * n;
    for (int t = tid; t < total; t += blockDim.x) {
        int w = t / n;
        int i = t - w * n;
        if (w < (i >> 5)) { mask[i * MSTRIDE + w] = 0u; continue; }
        float iy1 = sy1[i], ix1 = sx1[i], iy2 = sy2[i], ix2 = sx2[i];
        float ia = sarea[i];
        unsigned int mw = 0u;
        int jb = w << 5;
#pragma unroll 8
        for (int b = 0; b < 32; b++) {
            int j = jb + b;
            if (j > i && j < n) {
                float ih  = fminf(iy2, sy2[j]) - fmaxf(iy1, sy1[j]) + 1.0f;
                float iw2 = fminf(ix2, sx2[j]) - fmaxf(ix1, sx1[j]) + 1.0f;
                ih = fmaxf(ih, 0.0f); iw2 = fmaxf(iw2, 0.0f);
                float inter = ih * iw2;
                if (inter >= 0.5f * (ia + sarea[j] - inter)) mw |= (1u << b);
            }
        }
        mask[i * MSTRIDE + w] = mw;
    }
    __syncthreads();

    // greedy bit-reduce (warp 0), visiting only still-alive boxes via ffs
    if (tid < 32) {
        unsigned int remv = 0u;
        for (int c = 0; c < nw; c++) {
            unsigned int alive = ~__shfl_sync(0xFFFFFFFFu, remv, c);
            if (c == nw - 1 && (n & 31)) alive &= (1u << (n & 31)) - 1u;
            while (alive) {
                int b = __ffs(alive) - 1;
                int i = (c << 5) + b;
                unsigned int row = (tid < nw) ? mask[i * MSTRIDE + tid] : 0u;
                remv |= row;
                unsigned int rowc = __shfl_sync(0xFFFFFFFFu, row, c);
                alive &= ~rowc;
                alive &= ~(1u << b);
            }
        }
        s_remv[tid] = remv;
    }
    __syncthreads();

    for (int j = tid; j < n; j += blockDim.x)
        out[spos[j] * 6 + 5] = ((s_remv[j >> 5] >> (j & 31)) & 1u) ? 0.0f : 1.0f;
}

// ---------------- launch ----------------
extern "C" void kernel_launch(void* const* d_in, const int* in_sizes, int n_in,
                              void* d_out, int out_size) {
    const float* probs   = (const float*)d_in[0];
    const float* deltas  = (const float*)d_in[1];
    const float* anchors = (const float*)d_in[2];
    float* out = (float*)d_out;

    int n_prop    = in_sizes[0] / 3;
    int n_anchors = in_sizes[2] / 4;
    int n_groups  = n_prop / 4;          // 4 props (12 floats = 3 float4) per thread-step

    const int nms_smem = NMS_CAP * (5 * 4 + 4 + MSTRIDE * 4);   // 156672 bytes
    static int attr_set = 0;
    if (!attr_set) {
        cudaFuncSetAttribute(k_nms, cudaFuncAttributeMaxDynamicSharedMemorySize, nms_smem);
        attr_set = 1;
    }

    int gb1 = (n_groups + 511) / 512;    // 1 group per thread
    int gb2 = (n_groups + 255) / 256;

    k_hist<<<gb1, 512>>>(probs, n_groups);
    k_hist2<<<gb2, 256>>>(probs, n_groups);
    k_collect<<<gb2, 256>>>(probs, n_groups);
    k_rank<<<128, 1024>>>(deltas, anchors, out, n_anchors);
    k_nms<<<NGROUPS, 1024, nms_smem>>>(out);
}

// round 10
// speedup vs baseline: 1.3342x; 1.0191x over previous
#include <cuda_runtime.h>
#include <math.h>

#define K_TOP    6000
#define CAND_CAP 16384
#define BIN_CAP  16384
#define NMS_CAP  1024
#define HBINS    4096      // 12-bit histogram (top 12 bits of transformed score)
#define H2BINS   4096      // 12-bit refine histogram (bits [8,20))
#define MSTRIDE  33        // padded mask row stride (no 32-way bank conflicts)
#define NGROUPS  16
#define RTILE    1024      // ulonglong2 pairs per rank smem tile

// ---------------- scratch (device globals; no allocations) ----------------
__device__ unsigned int       g_hist[HBINS];
__device__ unsigned int       g_hist2[H2BINS];
__device__ unsigned int       g_meta[8];     // [3]=candidate counter [4]=bin counter
__device__ unsigned long long g_cand[CAND_CAP];
__device__ unsigned long long g_bin[BIN_CAP];
__device__ float4             g_gbox[NGROUPS * NMS_CAP];
__device__ int                g_gpos[NGROUPS * NMS_CAP];
__device__ unsigned int       g_gcnt[NGROUPS];

// order-preserving float<->uint transform
__device__ __forceinline__ unsigned int f2u(float f) {
    unsigned int b = __float_as_uint(f);
    return b ^ ((b & 0x80000000u) ? 0xFFFFFFFFu : 0x80000000u);
}
__device__ __forceinline__ float u2f(unsigned int u) {
    unsigned int b = (u & 0x80000000u) ? (u ^ 0x80000000u) : ~u;
    return __uint_as_float(b);
}

// warp-ballot-aggregated append of `key` when `e` is true
__device__ __forceinline__ void ballot_append(bool e, unsigned long long key,
                                              unsigned long long* buf,
                                              unsigned int* ctr,
                                              int lane, unsigned int cap) {
    unsigned int act = __activemask();
    unsigned int ball = __ballot_sync(act, e);
    if (!ball) return;
    int leader = __ffs(ball) - 1;
    unsigned int posb = 0;
    if (lane == leader) posb = atomicAdd(ctr, (unsigned int)__popc(ball));
    posb = __shfl_sync(act, posb, leader);
    if (e) {
        unsigned int my = posb + __popc(ball & ((1u << lane) - 1u));
        if (my < cap) buf[my] = key;
    }
}

// block-wide suffix-sum threshold find over histogram H[BINS]
template<int BINS, int NT>
__device__ __forceinline__ void find_threshold(const unsigned int* H,
                                               unsigned int need,
                                               unsigned int* ssum,
                                               volatile unsigned int* o_t,
                                               volatile unsigned int* o_cnt) {
    int tid = threadIdx.x;
    const int bpt = BINS / NT;
    unsigned int cs = 0;
    int base = tid * bpt;
#pragma unroll
    for (int k = 0; k < bpt; k++) cs += H[base + k];
    ssum[tid] = cs; __syncthreads();
    for (int off = 1; off < NT; off <<= 1) {           // inclusive suffix sum
        unsigned int v = (tid + off < NT) ? ssum[tid + off] : 0u;
        __syncthreads();
        ssum[tid] += v;
        __syncthreads();
    }
    unsigned int excl = (tid < NT - 1) ? ssum[tid + 1] : 0u;
    if (ssum[tid] >= need && excl < need) {            // unique crossing chunk
        unsigned int run = excl;
        for (int k = bpt - 1; k >= 0; k--) {
            unsigned int h = H[base + k];
            if (run + h >= need) { *o_t = (unsigned int)(base + k); *o_cnt = run; break; }
            run += h;
        }
    }
    __syncthreads();
}

// ---------------- kernel 1: 12-bit histogram of fg scores ----------------
__global__ void k_hist(const float* __restrict__ probs, int n_groups) {
    __shared__ unsigned int sh[HBINS];
    for (int k = threadIdx.x; k < HBINS; k += blockDim.x) sh[k] = 0u;
    __syncthreads();

    const float4* __restrict__ p4 = (const float4*)probs;
    int stride = gridDim.x * blockDim.x;
    for (int g = blockIdx.x * blockDim.x + threadIdx.x; g < n_groups; g += stride) {
        float4 A = p4[g * 3 + 0], B = p4[g * 3 + 1], C = p4[g * 3 + 2];
        float s[8] = {A.y, A.z, B.x, B.y, B.w, C.x, C.z, C.w};
#pragma unroll
        for (int k = 0; k < 8; k++) {
            unsigned int bin = f2u(s[k]) >> 20;
            unsigned int act = __activemask();
            unsigned int peers = __match_any_sync(act, bin);
            int leader = __ffs(peers) - 1;
            if ((threadIdx.x & 31) == leader)
                atomicAdd(&sh[bin], (unsigned int)__popc(peers));
        }
    }
    __syncthreads();
    for (int k = threadIdx.x; k < HBINS; k += blockDim.x) {
        unsigned int v = sh[k];
        if (v) atomicAdd(&g_hist[k], v);
    }
}

// --- kernel 2: fused refine-histogram + definite collect + bin stash ---
// keys strictly above the crossing 12-bit bin -> g_cand (definitely top-K pool)
// keys inside the crossing bin            -> g_bin + refine histogram
__global__ void k_hist2c(const float* __restrict__ probs, int n_groups) {
    __shared__ unsigned int sh[H2BINS];
    __shared__ unsigned int ssum[256];
    __shared__ unsigned int s_t, s_cnt;

    find_threshold<HBINS, 256>(g_hist, (unsigned)K_TOP, ssum, &s_t, &s_cnt);
    unsigned int t = s_t;

    for (int k = threadIdx.x; k < H2BINS; k += blockDim.x) sh[k] = 0u;
    __syncthreads();

    int lane = threadIdx.x & 31;
    const float4* __restrict__ p4 = (const float4*)probs;
    int stride = gridDim.x * blockDim.x;
    for (int g = blockIdx.x * blockDim.x + threadIdx.x; g < n_groups; g += stride) {
        float4 A = p4[g * 3 + 0], B = p4[g * 3 + 1], C = p4[g * 3 + 2];
        float s[8] = {A.y, A.z, B.x, B.y, B.w, C.x, C.z, C.w};
#pragma unroll
        for (int k = 0; k < 8; k++) {
            unsigned int u = f2u(s[k]);
            unsigned int hi = u >> 20;
            unsigned int flat = (unsigned int)((g * 4 + (k >> 1)) * 2 + (k & 1));
            unsigned long long key = ((unsigned long long)u << 32) |
                                     (unsigned long long)(0xFFFFFFFFu - flat);
            ballot_append(hi > t, key, g_cand, &g_meta[3], lane, CAND_CAP);
            bool inbin = (hi == t);
            ballot_append(inbin, key, g_bin, &g_meta[4], lane, BIN_CAP);
            if (inbin) atomicAdd(&sh[(u >> 8) & 0xFFFu], 1u);
        }
    }
    __syncthreads();
    for (int k = threadIdx.x; k < H2BINS; k += blockDim.x) {
        unsigned int v = sh[k];
        if (v) atomicAdd(&g_hist2[k], v);
    }
}

// --- kernel 3: filter bin keys by the refined 24-bit threshold, append ---
__global__ void k_filter() {
    __shared__ unsigned int ssum[256];
    __shared__ unsigned int s_t, s_cnt, s_t2, s_dum;
    int lane = threadIdx.x & 31;

    find_threshold<HBINS, 256>(g_hist, (unsigned)K_TOP, ssum, &s_t, &s_cnt);
    unsigned int need2 = (unsigned)K_TOP - s_cnt;
    find_threshold<H2BINS, 256>(g_hist2, need2, ssum, &s_t2, &s_dum);
    unsigned int t2 = s_t2;

    int nb = (int)min(g_meta[4], (unsigned int)BIN_CAP);
    int stride = gridDim.x * blockDim.x;
    for (int i = blockIdx.x * blockDim.x + threadIdx.x; i < nb; i += stride) {
        unsigned long long key = g_bin[i];
        unsigned int u = (unsigned int)(key >> 32);
        bool e = ((u >> 8) & 0xFFFu) >= t2;    // prefix == t12 for all bin keys
        ballot_append(e, key, g_cand, &g_meta[3], lane, CAND_CAP);
    }
}

// --- kernel 4: exact global rank via smem-tiled compare-count + decode ---
__global__ __launch_bounds__(1024, 1)
void k_rank(const float* __restrict__ deltas,
            const float* __restrict__ anchors,
            float* __restrict__ out, int n_anchors) {
    __shared__ ulonglong2 tile[RTILE];      // 16KB
    int m = (int)min(g_meta[3], (unsigned int)CAND_CAP);
    int lane = threadIdx.x & 31;
    int wid  = threadIdx.x >> 5;
    int c0 = (blockIdx.x * 32 + wid) * 2;

    unsigned long long ck0 = (c0 < m)     ? g_cand[c0]     : 0xFFFFFFFFFFFFFFFFULL;
    unsigned long long ck1 = (c0 + 1 < m) ? g_cand[c0 + 1] : 0xFFFFFFFFFFFFFFFFULL;
    unsigned int cnt0 = 0u, cnt1 = 0u;

    const ulonglong2* __restrict__ p2 = (const ulonglong2*)g_cand;
    int mp = (m + 1) >> 1;                  // pairs; pad slot m is provably 0
    for (int t0 = 0; t0 < mp; t0 += RTILE) {
        int nt = min(RTILE, mp - t0);
        for (int i = threadIdx.x; i < nt; i += 1024) tile[i] = p2[t0 + i];
        __syncthreads();
        int j = lane;
        for (; j + 96 < nt; j += 128) {     // 4-wide unroll: 8 keys / iter
            ulonglong2 a = tile[j], b = tile[j + 32];
            ulonglong2 c = tile[j + 64], d = tile[j + 96];
            cnt0 += (a.x > ck0) ? 1u : 0u;  cnt0 += (a.y > ck0) ? 1u : 0u;
            cnt1 += (a.x > ck1) ? 1u : 0u;  cnt1 += (a.y > ck1) ? 1u : 0u;
            cnt0 += (b.x > ck0) ? 1u : 0u;  cnt0 += (b.y > ck0) ? 1u : 0u;
            cnt1 += (b.x > ck1) ? 1u : 0u;  cnt1 += (b.y > ck1) ? 1u : 0u;
            cnt0 += (c.x > ck0) ? 1u : 0u;  cnt0 += (c.y > ck0) ? 1u : 0u;
            cnt1 += (c.x > ck1) ? 1u : 0u;  cnt1 += (c.y > ck1) ? 1u : 0u;
            cnt0 += (d.x > ck0) ? 1u : 0u;  cnt0 += (d.y > ck0) ? 1u : 0u;
            cnt1 += (d.x > ck1) ? 1u : 0u;  cnt1 += (d.y > ck1) ? 1u : 0u;
        }
        for (; j < nt; j += 32) {
            ulonglong2 kk = tile[j];
            cnt0 += (kk.x > ck0) ? 1u : 0u; cnt0 += (kk.y > ck0) ? 1u : 0u;
            cnt1 += (kk.x > ck1) ? 1u : 0u; cnt1 += (kk.y > ck1) ? 1u : 0u;
        }
        __syncthreads();
    }
#pragma unroll
    for (int off = 16; off > 0; off >>= 1) {
        cnt0 += __shfl_down_sync(0xFFFFFFFFu, cnt0, off);
        cnt1 += __shfl_down_sync(0xFFFFFFFFu, cnt1, off);
    }

    if (lane == 0 && c0 < m) {
#pragma unroll
        for (int which = 0; which < 2; which++) {
            int c = c0 + which;
            if (c >= m) break;
            unsigned int cnt = which ? cnt1 : cnt0;
            if (cnt >= (unsigned)K_TOP) continue;
            unsigned long long ckey = which ? ck1 : ck0;

            int rk = (int)cnt;
            unsigned int u = (unsigned int)(ckey >> 32);
            unsigned int flat = 0xFFFFFFFFu - (unsigned int)(ckey & 0xFFFFFFFFu);
            int prop = (int)(flat >> 1);
            int cls = (int)(flat & 1u) + 1;
            float score = u2f(u);
            int b = prop / n_anchors;
            int ai = prop - b * n_anchors;

            const float* a  = anchors + (size_t)ai * 4;
            const float* dl = deltas + (size_t)prop * 4;
            float d0 = dl[0] * 0.1f, d1 = dl[1] * 0.1f;
            float d2 = dl[2] * 0.2f, d3 = dl[3] * 0.2f;

            const float inv = 1.0f / 512.0f;
            float ay1 = a[0] * inv, ax1 = a[1] * inv;
            float ay2 = a[2] * inv, ax2 = a[3] * inv;
            float h  = ay2 - ay1;
            float w2 = ax2 - ax1;
            float cy = ay1 + 0.5f * h + d0 * h;
            float cx = ax1 + 0.5f * w2 + d1 * w2;
            h  = h * expf(d2);
            w2 = w2 * expf(d3);
            float y1 = cy - 0.5f * h;
            float x1 = cx - 0.5f * w2;
            float y2 = y1 + h;
            float x2 = x1 + w2;
            y1 = fminf(fmaxf(y1 * 512.0f, 0.0f), 512.0f);
            x1 = fminf(fmaxf(x1 * 512.0f, 0.0f), 512.0f);
            y2 = fminf(fmaxf(y2 * 512.0f, 0.0f), 512.0f);
            x2 = fminf(fmaxf(x2 * 512.0f, 0.0f), 512.0f);

            out[rk * 6 + 0] = y1;
            out[rk * 6 + 1] = x1;
            out[rk * 6 + 2] = y2;
            out[rk * 6 + 3] = x2;
            out[rk * 6 + 4] = score;
            out[rk * 6 + 5] = 1.0f;                 // keep (finalized by NMS)
            out[K_TOP * 6 + rk] = (float)cls;       // class_ids
            out[K_TOP * 7 + rk] = (float)b;         // batch ids

            int grp = b * 2 + (int)(flat & 1u);
            unsigned int slot = atomicAdd(&g_gcnt[grp], 1u);   // arbitrary order
            if (slot < NMS_CAP) {
                g_gbox[grp * NMS_CAP + slot] = make_float4(y1, x1, y2, x2);
                g_gpos[grp * NMS_CAP + slot] = rk;
            }
        }
    }
}

// ------- kernel 5: per-group NMS (sorts by global rank first) + cleanup -------
__global__ void k_nms(float* __restrict__ out) {
    extern __shared__ unsigned char dyn[];
    float* sy1   = (float*)dyn;
    float* sx1   = sy1 + NMS_CAP;
    float* sy2   = sx1 + NMS_CAP;
    float* sx2   = sy2 + NMS_CAP;
    float* sarea = sx2 + NMS_CAP;
    int* spos    = (int*)(sarea + NMS_CAP);
    unsigned int* mask = (unsigned int*)(spos + NMS_CAP);   // [NMS_CAP][MSTRIDE]
    int* rkraw = (int*)mask;                                // pre-mask scratch

    __shared__ unsigned int s_remv[32];

    int tid = threadIdx.x;
    int grp = blockIdx.x;

    // cleanup scratch for next graph replay
    if (tid < HBINS / NGROUPS) g_hist[grp * (HBINS / NGROUPS) + tid] = 0u;
    else if (tid >= 256 && tid < 256 + H2BINS / NGROUPS)
        g_hist2[grp * (H2BINS / NGROUPS) + (tid - 256)] = 0u;
    if (grp == 0 && tid == 512) g_meta[3] = 0u;
    if (grp == 0 && tid == 513) g_meta[4] = 0u;

    int n = min((int)g_gcnt[grp], NMS_CAP);

    // load raw (unordered) entries; sort by global rank via rank-by-count
    float4 bx = make_float4(0.f, 0.f, 0.f, 0.f);
    int ps = 0;
    if (tid < n) {
        bx = g_gbox[grp * NMS_CAP + tid];
        ps = g_gpos[grp * NMS_CAP + tid];
        rkraw[tid] = ps;
    }
    __syncthreads();
    if (tid == 0) g_gcnt[grp] = 0u;
    int myrank = 0;
    if (tid < n)
        for (int j = 0; j < n; j++) myrank += (rkraw[j] < ps) ? 1 : 0;
    __syncthreads();
    if (tid < n) {
        sy1[myrank] = bx.x; sx1[myrank] = bx.y;
        sy2[myrank] = bx.z; sx2[myrank] = bx.w;
        sarea[myrank] = (bx.z - bx.x + 1.0f) * (bx.w - bx.y + 1.0f);
        spos[myrank] = ps;
    }
    __syncthreads();

    int nw = (n + 31) >> 5;

    // forward suppression masks; t = w*n + i (i fastest): lanes share w,
    // consecutive i -> conflict-free mask stores with MSTRIDE=33
    int total = nw * n;
    for (int t = tid; t < total; t += blockDim.x) {
        int w = t / n;
        int i = t - w * n;
        if (w < (i >> 5)) { mask[i * MSTRIDE + w] = 0u; continue; }
        float iy1 = sy1[i], ix1 = sx1[i], iy2 = sy2[i], ix2 = sx2[i];
        float ia = sarea[i];
        unsigned int mw = 0u;
        int jb = w << 5;
#pragma unroll 8
        for (int b = 0; b < 32; b++) {
            int j = jb + b;
            if (j > i && j < n) {
                float ih  = fminf(iy2, sy2[j]) - fmaxf(iy1, sy1[j]) + 1.0f;
                float iw2 = fminf(ix2, sx2[j]) - fmaxf(ix1, sx1[j]) + 1.0f;
                ih = fmaxf(ih, 0.0f); iw2 = fmaxf(iw2, 0.0f);
                float inter = ih * iw2;
                if (inter >= 0.5f * (ia + sarea[j] - inter)) mw |= (1u << b);
            }
        }
        mask[i * MSTRIDE + w] = mw;
    }
    __syncthreads();

    // greedy bit-reduce (warp 0), visiting only still-alive boxes via ffs
    if (tid < 32) {
        unsigned int remv = 0u;
        for (int c = 0; c < nw; c++) {
            unsigned int alive = ~__shfl_sync(0xFFFFFFFFu, remv, c);
            if (c == nw - 1 && (n & 31)) alive &= (1u << (n & 31)) - 1u;
            while (alive) {
                int b = __ffs(alive) - 1;
                int i = (c << 5) + b;
                unsigned int row = (tid < nw) ? mask[i * MSTRIDE + tid] : 0u;
                remv |= row;
                unsigned int rowc = __shfl_sync(0xFFFFFFFFu, row, c);
                alive &= ~rowc;
                alive &= ~(1u << b);
            }
        }
        s_remv[tid] = remv;
    }
    __syncthreads();

    for (int j = tid; j < n; j += blockDim.x)
        out[spos[j] * 6 + 5] = ((s_remv[j >> 5] >> (j & 31)) & 1u) ? 0.0f : 1.0f;
}

// ---------------- launch ----------------
extern "C" void kernel_launch(void* const* d_in, const int* in_sizes, int n_in,
                              void* d_out, int out_size) {
    const float* probs   = (const float*)d_in[0];
    const float* deltas  = (const float*)d_in[1];
    const float* anchors = (const float*)d_in[2];
    float* out = (float*)d_out;

    int n_prop    = in_sizes[0] / 3;
    int n_anchors = in_sizes[2] / 4;
    int n_groups  = n_prop / 4;          // 4 props (12 floats = 3 float4) per thread-step

    const int nms_smem = NMS_CAP * (5 * 4 + 4 + MSTRIDE * 4);   // 156672 bytes
    static int attr_set = 0;
    if (!attr_set) {
        cudaFuncSetAttribute(k_nms, cudaFuncAttributeMaxDynamicSharedMemorySize, nms_smem);
        attr_set = 1;
    }

    int gb1 = (n_groups + 511) / 512;    // 1 group per thread
    int gb2 = (n_groups + 255) / 256;

    k_hist<<<gb1, 512>>>(probs, n_groups);
    k_hist2c<<<gb2, 256>>>(probs, n_groups);
    k_filter<<<16, 256>>>();
    k_rank<<<128, 1024>>>(deltas, anchors, out, n_anchors);
    k_nms<<<NGROUPS, 1024, nms_smem>>>(out);
}